// round 4
// baseline (speedup 1.0000x reference)
#include <cuda_runtime.h>
#include <cstdint>
#include <math.h>

// ---------------------------------------------------------------------------
// Problem constants
// ---------------------------------------------------------------------------
#define BATCH 4
#define SEQ   2048
#define FDIM  1024
#define DKDIM 1024

// ---------------------------------------------------------------------------
// mma.sync tf32 GEMM tiling
// ---------------------------------------------------------------------------
#define BM 128
#define BN 128
#define BK 32
#define STAGES 2
#define GEMM_THREADS 256

#define ROWF 36                            // padded row length in floats (BK + 4)
#define A_STAGE_FLOATS (BM * ROWF)         // 4608
#define STAGE_FLOATS   (2 * A_STAGE_FLOATS)
#define GEMM_SMEM      (STAGES * STAGE_FLOATS * 4)   // 73,728 B

// ---------------------------------------------------------------------------
// Scratch (device globals — no dynamic allocation allowed)
// ---------------------------------------------------------------------------
__device__ float g_x  [(size_t)BATCH * SEQ * FDIM];
__device__ float g_q  [(size_t)BATCH * SEQ * DKDIM];
__device__ float g_k  [(size_t)BATCH * SEQ * DKDIM];
__device__ float g_v  [(size_t)BATCH * SEQ * DKDIM];
__device__ float g_vt [(size_t)BATCH * DKDIM * SEQ];
__device__ float g_sc [(size_t)BATCH * SEQ * SEQ];
__device__ float g_ctx[(size_t)BATCH * SEQ * DKDIM];
__device__ float g_wqt[(size_t)DKDIM * FDIM];
__device__ float g_wkt[(size_t)DKDIM * FDIM];
__device__ float g_wvt[(size_t)DKDIM * FDIM];
__device__ float g_wot[(size_t)FDIM * DKDIM];

// ---------------------------------------------------------------------------
// Helpers
// ---------------------------------------------------------------------------
__device__ __forceinline__ uint32_t smem_u32(const void* p) {
    uint32_t a;
    asm("{ .reg .u64 t; cvta.to.shared.u64 t, %1; cvt.u32.u64 %0, t; }" : "=r"(a) : "l"(p));
    return a;
}
__device__ __forceinline__ float tf32_rn(float v) {
    uint32_t r;
    asm("cvt.rn.tf32.f32 %0, %1;" : "=r"(r) : "f"(v));
    return __uint_as_float(r);
}
__device__ __forceinline__ void cp_async16(uint32_t dst, const void* src) {
    asm volatile("cp.async.cg.shared.global [%0], [%1], 16;" :: "r"(dst), "l"(src) : "memory");
}
__device__ __forceinline__ void cp_commit() {
    asm volatile("cp.async.commit_group;" ::: "memory");
}
__device__ __forceinline__ void cp_wait_1() {
    asm volatile("cp.async.wait_group 1;" ::: "memory");
}
__device__ __forceinline__ void mma_tf32(float* d, const uint32_t* a, const uint32_t* b) {
    asm volatile(
        "mma.sync.aligned.m16n8k8.row.col.f32.tf32.tf32.f32 "
        "{%0,%1,%2,%3}, {%4,%5,%6,%7}, {%8,%9}, {%0,%1,%2,%3};"
        : "+f"(d[0]), "+f"(d[1]), "+f"(d[2]), "+f"(d[3])
        : "r"(a[0]), "r"(a[1]), "r"(a[2]), "r"(a[3]), "r"(b[0]), "r"(b[1]));
}

// ---------------------------------------------------------------------------
// tf32 tensor-core GEMM:  C = alpha * A * B^T + bias
//   A: [M,K] row-major (batched by sA)
//   B: [N,K] row-major (batched by sB)
//   C: [M,N] row-major (batched by sC)
// M,N % 128 == 0, K % 32 == 0 (holds for every shape here).
// ---------------------------------------------------------------------------
__global__ void __launch_bounds__(GEMM_THREADS, 2)
gemm_tf32_kernel(const float* __restrict__ A, const float* __restrict__ B,
                 const float* __restrict__ bias, float* __restrict__ C,
                 int M, int N, int K,
                 long long sA, long long sB, long long sC,
                 float alpha, int round_out)
{
    extern __shared__ float sm[];
    const int tid = threadIdx.x;
    const int wid = tid >> 5;
    const int lane = tid & 31;
    const int g   = lane >> 2;     // 0..7
    const int tig = lane & 3;      // 0..3
    const int mw = (wid >> 2) * 64;    // warp m offset in tile
    const int nw = (wid & 3) * 32;     // warp n offset in tile

    A += (long long)blockIdx.z * sA;
    B += (long long)blockIdx.z * sB;
    C += (long long)blockIdx.z * sC;
    const int m0 = blockIdx.y * BM;
    const int n0 = blockIdx.x * BN;

    float acc[4][4][4];
#pragma unroll
    for (int mt = 0; mt < 4; mt++)
#pragma unroll
        for (int nt = 0; nt < 4; nt++)
#pragma unroll
            for (int r = 0; r < 4; r++) acc[mt][nt][r] = 0.0f;

    const uint32_t sm_base = smem_u32(sm);
    const int KT = K / BK;

    auto load_stage = [&](int p) {
        const uint32_t base = sm_base + (uint32_t)((p & 1) * STAGE_FLOATS) * 4u;
        const uint32_t bbase = base + A_STAGE_FLOATS * 4u;
        const int k0 = p * BK;
#pragma unroll
        for (int t = 0; t < 4; t++) {                    // A: 1024 chunks of 16B
            int c = tid + t * GEMM_THREADS;
            int r = c >> 3, kc = c & 7;
            cp_async16(base + (uint32_t)(r * ROWF + kc * 4) * 4u,
                       A + (long long)(m0 + r) * K + k0 + kc * 4);
        }
#pragma unroll
        for (int t = 0; t < 4; t++) {                    // B: 1024 chunks of 16B
            int c = tid + t * GEMM_THREADS;
            int r = c >> 3, kc = c & 7;
            cp_async16(bbase + (uint32_t)(r * ROWF + kc * 4) * 4u,
                       B + (long long)(n0 + r) * K + k0 + kc * 4);
        }
    };

    load_stage(0);
    cp_commit();

    for (int kt = 0; kt < KT; kt++) {
        if (kt + 1 < KT) load_stage(kt + 1);
        cp_commit();
        cp_wait_1();                   // group kt fully resident
        __syncthreads();

        const float* sa = sm + (kt & 1) * STAGE_FLOATS;
        const float* sb = sa + A_STAGE_FLOATS;
#pragma unroll
        for (int kk = 0; kk < 4; kk++) {
            const int k8 = kk * 8;
            uint32_t a[4][4], b[4][2];
#pragma unroll
            for (int mt = 0; mt < 4; mt++) {
                const float* pa = sa + (mw + mt * 16 + g) * ROWF + k8 + tig;
                a[mt][0] = __float_as_uint(pa[0]);
                a[mt][1] = __float_as_uint(pa[8 * ROWF]);
                a[mt][2] = __float_as_uint(pa[4]);
                a[mt][3] = __float_as_uint(pa[8 * ROWF + 4]);
            }
#pragma unroll
            for (int nt = 0; nt < 4; nt++) {
                const float* pb = sb + (nw + nt * 8 + g) * ROWF + k8 + tig;
                b[nt][0] = __float_as_uint(pb[0]);
                b[nt][1] = __float_as_uint(pb[4]);
            }
#pragma unroll
            for (int mt = 0; mt < 4; mt++)
#pragma unroll
                for (int nt = 0; nt < 4; nt++)
                    mma_tf32(acc[mt][nt], a[mt], b[nt]);
        }
        __syncthreads();               // stage slot safe to overwrite next iter
    }

    // ---- epilogue ----
#pragma unroll
    for (int mt = 0; mt < 4; mt++) {
        const int m = m0 + mw + mt * 16 + g;
#pragma unroll
        for (int nt = 0; nt < 4; nt++) {
            const int n = n0 + nw + nt * 8 + 2 * tig;
            float2 v0, v1;
            v0.x = acc[mt][nt][0] * alpha;
            v0.y = acc[mt][nt][1] * alpha;
            v1.x = acc[mt][nt][2] * alpha;
            v1.y = acc[mt][nt][3] * alpha;
            if (bias) {
                float bx = bias[n], by = bias[n + 1];
                v0.x += bx; v0.y += by;
                v1.x += bx; v1.y += by;
            }
            if (round_out) {
                v0.x = tf32_rn(v0.x); v0.y = tf32_rn(v0.y);
                v1.x = tf32_rn(v1.x); v1.y = tf32_rn(v1.y);
            }
            *(float2*)(C + (long long)m * N + n)       = v0;
            *(float2*)(C + (long long)(m + 8) * N + n) = v1;
        }
    }
}

// ---------------------------------------------------------------------------
// tf32-round copy (for x)
// ---------------------------------------------------------------------------
__global__ void __launch_bounds__(256)
round_tf32_kernel(const float* __restrict__ in, float* __restrict__ out)
{
    size_t i = (size_t)blockIdx.x * blockDim.x + threadIdx.x;
    float4 v = ((const float4*)in)[i];
    v.x = tf32_rn(v.x); v.y = tf32_rn(v.y); v.z = tf32_rn(v.z); v.w = tf32_rn(v.w);
    ((float4*)out)[i] = v;
}

// ---------------------------------------------------------------------------
// Batched transpose: in [R,C] -> out [C,R], optional tf32 rounding
// ---------------------------------------------------------------------------
__global__ void __launch_bounds__(256)
transpose_kernel(const float* __restrict__ in, float* __restrict__ out,
                 int R, int C, long long sIn, long long sOut, int do_round)
{
    __shared__ float t[32][33];
    in  += (long long)blockIdx.z * sIn;
    out += (long long)blockIdx.z * sOut;
    const int c0 = blockIdx.x * 32, r0 = blockIdx.y * 32;
#pragma unroll
    for (int i = 0; i < 32; i += 8)
        t[threadIdx.y + i][threadIdx.x] =
            in[(long long)(r0 + threadIdx.y + i) * C + c0 + threadIdx.x];
    __syncthreads();
#pragma unroll
    for (int i = 0; i < 32; i += 8) {
        float v = t[threadIdx.x][threadIdx.y + i];
        if (do_round) v = tf32_rn(v);
        out[(long long)(c0 + threadIdx.y + i) * R + r0 + threadIdx.x] = v;
    }
}

// ---------------------------------------------------------------------------
// Softmax over the QUERY axis (axis=-2), coalesced over k; writes tf32-rounded
// ---------------------------------------------------------------------------
__global__ void __launch_bounds__(256)
softmax_over_q_kernel(float* __restrict__ scores)
{
    const int b = blockIdx.y;
    const int k = blockIdx.x * blockDim.x + threadIdx.x;
    float* p = scores + (long long)b * SEQ * SEQ + k;

    float m = -INFINITY;
    for (int q = 0; q < SEQ; q++) m = fmaxf(m, p[(long long)q * SEQ]);
    float sum = 0.0f;
    for (int q = 0; q < SEQ; q++) sum += expf(p[(long long)q * SEQ] - m);
    float inv = 1.0f / sum;
    for (int q = 0; q < SEQ; q++) {
        float v = expf(p[(long long)q * SEQ] - m) * inv;
        p[(long long)q * SEQ] = tf32_rn(v);
    }
}

// ---------------------------------------------------------------------------
// Launcher
// ---------------------------------------------------------------------------
extern "C" void kernel_launch(void* const* d_in, const int* in_sizes, int n_in,
                              void* d_out, int out_size)
{
    const float* x  = (const float*)d_in[0];
    const float* Wq = (const float*)d_in[1];
    const float* bq = (const float*)d_in[2];
    const float* Wk = (const float*)d_in[3];
    const float* bk = (const float*)d_in[4];
    const float* Wv = (const float*)d_in[5];
    const float* bv = (const float*)d_in[6];
    const float* Wo = (const float*)d_in[7];
    const float* bo = (const float*)d_in[8];
    float* out = (float*)d_out;

    float *xr, *q, *k, *v, *vt, *sc, *ctx, *wqt, *wkt, *wvt, *wot;
    cudaGetSymbolAddress((void**)&xr,  g_x);
    cudaGetSymbolAddress((void**)&q,   g_q);
    cudaGetSymbolAddress((void**)&k,   g_k);
    cudaGetSymbolAddress((void**)&v,   g_v);
    cudaGetSymbolAddress((void**)&vt,  g_vt);
    cudaGetSymbolAddress((void**)&sc,  g_sc);
    cudaGetSymbolAddress((void**)&ctx, g_ctx);
    cudaGetSymbolAddress((void**)&wqt, g_wqt);
    cudaGetSymbolAddress((void**)&wkt, g_wkt);
    cudaGetSymbolAddress((void**)&wvt, g_wvt);
    cudaGetSymbolAddress((void**)&wot, g_wot);

    cudaFuncSetAttribute(gemm_tf32_kernel,
                         cudaFuncAttributeMaxDynamicSharedMemorySize, GEMM_SMEM);

    const int MS = BATCH * SEQ;                        // 8192
    const long long sQK = (long long)SEQ * DKDIM;
    const long long sSS = (long long)SEQ * SEQ;
    const float inv_sqrt_dk = 1.0f / 32.0f;

    // 0) round x to tf32, transpose+round weights
    round_tf32_kernel<<<(BATCH * SEQ * FDIM / 4) / 256, 256>>>(x, xr);
    {
        dim3 blk(32, 8);
        dim3 g1(DKDIM / 32, FDIM / 32, 1);
        transpose_kernel<<<g1, blk>>>(Wq, wqt, FDIM, DKDIM, 0, 0, 1);
        transpose_kernel<<<g1, blk>>>(Wk, wkt, FDIM, DKDIM, 0, 0, 1);
        transpose_kernel<<<g1, blk>>>(Wv, wvt, FDIM, DKDIM, 0, 0, 1);
        dim3 g2(FDIM / 32, DKDIM / 32, 1);
        transpose_kernel<<<g2, blk>>>(Wo, wot, DKDIM, FDIM, 0, 0, 1);
    }

    // 1) projections: [8192,1024] = xr * W^T + b  (outputs tf32-rounded)
    {
        dim3 grd(DKDIM / BN, MS / BM, 1);
        gemm_tf32_kernel<<<grd, GEMM_THREADS, GEMM_SMEM>>>(xr, wqt, bq, q, MS, DKDIM, FDIM, 0, 0, 0, 1.0f, 1);
        gemm_tf32_kernel<<<grd, GEMM_THREADS, GEMM_SMEM>>>(xr, wkt, bk, k, MS, DKDIM, FDIM, 0, 0, 0, 1.0f, 1);
        gemm_tf32_kernel<<<grd, GEMM_THREADS, GEMM_SMEM>>>(xr, wvt, bv, v, MS, DKDIM, FDIM, 0, 0, 0, 1.0f, 1);
    }

    // 2) scores = Q K^T / sqrt(dk)   (batched)
    {
        dim3 grd(SEQ / BN, SEQ / BM, BATCH);
        gemm_tf32_kernel<<<grd, GEMM_THREADS, GEMM_SMEM>>>(q, k, nullptr, sc, SEQ, SEQ, DKDIM,
                                                           sQK, sQK, sSS, inv_sqrt_dk, 0);
    }

    // 3) softmax over query axis (writes tf32-rounded attn)
    softmax_over_q_kernel<<<dim3(SEQ / 256, BATCH), 256>>>(sc);

    // 3b) V^T (per batch) for the attn*V GEMM
    {
        dim3 blk(32, 8);
        dim3 g(DKDIM / 32, SEQ / 32, BATCH);
        transpose_kernel<<<g, blk>>>(v, vt, SEQ, DKDIM, sQK, sQK, 0);
    }

    // 4) ctx = attn * V   (batched; B = V^T [DK, S] K-major)
    {
        dim3 grd(DKDIM / BN, SEQ / BM, BATCH);
        gemm_tf32_kernel<<<grd, GEMM_THREADS, GEMM_SMEM>>>(sc, vt, nullptr, ctx, SEQ, DKDIM, SEQ,
                                                           sSS, sQK, sQK, 1.0f, 1);
    }

    // 5) out = ctx * Wo + bo
    {
        dim3 grd(FDIM / BN, MS / BM, 1);
        gemm_tf32_kernel<<<grd, GEMM_THREADS, GEMM_SMEM>>>(ctx, wot, bo, out, MS, FDIM, DKDIM,
                                                           0, 0, 0, 1.0f, 0);
    }
}

// round 5
// speedup vs baseline: 1.1831x; 1.1831x over previous
#include <cuda_runtime.h>
#include <cstdint>
#include <math.h>

// ---------------------------------------------------------------------------
// Problem constants
// ---------------------------------------------------------------------------
#define BATCH 4
#define SEQ   2048
#define FDIM  1024
#define DKDIM 1024

// ---------------------------------------------------------------------------
// mma.sync tf32 GEMM tiling: CTA 128x256, warp 64x64, BK=32, 3 stages
// ---------------------------------------------------------------------------
#define BM 128
#define BN 256
#define BK 32
#define STAGES 3
#define GEMM_THREADS 256

#define ROWF 36                                 // padded row length (BK + 4)
#define A_STAGE_FLOATS (BM * ROWF)              // 4608
#define B_STAGE_FLOATS (BN * ROWF)              // 9216
#define STAGE_FLOATS   (A_STAGE_FLOATS + B_STAGE_FLOATS)
#define GEMM_SMEM      (STAGES * STAGE_FLOATS * 4)   // 165,888 B

// ---------------------------------------------------------------------------
// Scratch (device globals — no dynamic allocation allowed)
// ---------------------------------------------------------------------------
__device__ float g_x  [(size_t)BATCH * SEQ * FDIM];
__device__ float g_q  [(size_t)BATCH * SEQ * DKDIM];
__device__ float g_k  [(size_t)BATCH * SEQ * DKDIM];
__device__ float g_v  [(size_t)BATCH * SEQ * DKDIM];
__device__ float g_vt [(size_t)BATCH * DKDIM * SEQ];
__device__ float g_sc [(size_t)BATCH * SEQ * SEQ];
__device__ float g_ctx[(size_t)BATCH * SEQ * DKDIM];
__device__ float g_wqt[(size_t)DKDIM * FDIM];
__device__ float g_wkt[(size_t)DKDIM * FDIM];
__device__ float g_wvt[(size_t)DKDIM * FDIM];
__device__ float g_wot[(size_t)FDIM * DKDIM];

// ---------------------------------------------------------------------------
// Helpers
// ---------------------------------------------------------------------------
__device__ __forceinline__ uint32_t smem_u32(const void* p) {
    uint32_t a;
    asm("{ .reg .u64 t; cvta.to.shared.u64 t, %1; cvt.u32.u64 %0, t; }" : "=r"(a) : "l"(p));
    return a;
}
__device__ __forceinline__ float tf32_rn(float v) {
    uint32_t r;
    asm("cvt.rn.tf32.f32 %0, %1;" : "=r"(r) : "f"(v));
    return __uint_as_float(r);
}
__device__ __forceinline__ void cp_async16(uint32_t dst, const void* src) {
    asm volatile("cp.async.cg.shared.global [%0], [%1], 16;" :: "r"(dst), "l"(src) : "memory");
}
__device__ __forceinline__ void cp_commit() {
    asm volatile("cp.async.commit_group;" ::: "memory");
}
__device__ __forceinline__ void cp_wait_1() {
    asm volatile("cp.async.wait_group 1;" ::: "memory");
}
__device__ __forceinline__ void mma_tf32(float* d, const uint32_t* a, const uint32_t* b) {
    asm volatile(
        "mma.sync.aligned.m16n8k8.row.col.f32.tf32.tf32.f32 "
        "{%0,%1,%2,%3}, {%4,%5,%6,%7}, {%8,%9}, {%0,%1,%2,%3};"
        : "+f"(d[0]), "+f"(d[1]), "+f"(d[2]), "+f"(d[3])
        : "r"(a[0]), "r"(a[1]), "r"(a[2]), "r"(a[3]), "r"(b[0]), "r"(b[1]));
}

// ---------------------------------------------------------------------------
// tf32 tensor-core GEMM:  C = alpha * A * B^T + bias
//   A: [M,K] row-major (batched by sA)
//   B: [N,K] row-major (batched by sB)
//   C: [M,N] row-major (batched by sC)
// M % 128 == 0, N % 256 == 0, K % 32 == 0 (holds for every shape here).
// ---------------------------------------------------------------------------
__global__ void __launch_bounds__(GEMM_THREADS, 1)
gemm_tf32_kernel(const float* __restrict__ A, const float* __restrict__ B,
                 const float* __restrict__ bias, float* __restrict__ C,
                 int M, int N, int K,
                 long long sA, long long sB, long long sC,
                 float alpha, int round_out)
{
    extern __shared__ float sm[];
    const int tid = threadIdx.x;
    const int wid = tid >> 5;
    const int lane = tid & 31;
    const int g   = lane >> 2;         // 0..7
    const int tig = lane & 3;          // 0..3
    const int mw = (wid & 1) * 64;     // warp m offset (2 rows of warps)
    const int nw = (wid >> 1) * 64;    // warp n offset (4 cols of warps)

    A += (long long)blockIdx.z * sA;
    B += (long long)blockIdx.z * sB;
    C += (long long)blockIdx.z * sC;
    const int m0 = blockIdx.y * BM;
    const int n0 = blockIdx.x * BN;

    float acc[4][8][4];
#pragma unroll
    for (int mt = 0; mt < 4; mt++)
#pragma unroll
        for (int nt = 0; nt < 8; nt++)
#pragma unroll
            for (int r = 0; r < 4; r++) acc[mt][nt][r] = 0.0f;

    const uint32_t sm_base = smem_u32(sm);
    const int KT = K / BK;

    auto load_stage = [&](int p) {
        const uint32_t base = sm_base + (uint32_t)((p % STAGES) * STAGE_FLOATS) * 4u;
        const uint32_t bbase = base + A_STAGE_FLOATS * 4u;
        const int k0 = p * BK;
#pragma unroll
        for (int t = 0; t < 4; t++) {                // A: 1024 chunks of 16B
            int c = tid + t * GEMM_THREADS;
            int r = c >> 3, kc = c & 7;
            cp_async16(base + (uint32_t)(r * ROWF + kc * 4) * 4u,
                       A + (long long)(m0 + r) * K + k0 + kc * 4);
        }
#pragma unroll
        for (int t = 0; t < 8; t++) {                // B: 2048 chunks of 16B
            int c = tid + t * GEMM_THREADS;
            int r = c >> 3, kc = c & 7;
            cp_async16(bbase + (uint32_t)(r * ROWF + kc * 4) * 4u,
                       B + (long long)(n0 + r) * K + k0 + kc * 4);
        }
    };

    load_stage(0); cp_commit();
    load_stage(1); cp_commit();

    for (int kt = 0; kt < KT; kt++) {
        cp_wait_1();                     // stage kt resident
        __syncthreads();                 // all warps done with stage kt-1

        if (kt + 2 < KT) load_stage(kt + 2);
        cp_commit();

        const float* sa = sm + (kt % STAGES) * STAGE_FLOATS;
        const float* sb = sa + A_STAGE_FLOATS;
#pragma unroll
        for (int kk = 0; kk < 4; kk++) {
            const int k8 = kk * 8;
            uint32_t a[4][4], b[8][2];
#pragma unroll
            for (int mt = 0; mt < 4; mt++) {
                const float* pa = sa + (mw + mt * 16 + g) * ROWF + k8 + tig;
                a[mt][0] = __float_as_uint(pa[0]);
                a[mt][1] = __float_as_uint(pa[8 * ROWF]);
                a[mt][2] = __float_as_uint(pa[4]);
                a[mt][3] = __float_as_uint(pa[8 * ROWF + 4]);
            }
#pragma unroll
            for (int nt = 0; nt < 8; nt++) {
                const float* pb = sb + (nw + nt * 8 + g) * ROWF + k8 + tig;
                b[nt][0] = __float_as_uint(pb[0]);
                b[nt][1] = __float_as_uint(pb[4]);
            }
#pragma unroll
            for (int mt = 0; mt < 4; mt++)
#pragma unroll
                for (int nt = 0; nt < 8; nt++)
                    mma_tf32(acc[mt][nt], a[mt], b[nt]);
        }
    }

    // ---- epilogue ----
#pragma unroll
    for (int mt = 0; mt < 4; mt++) {
        const int m = m0 + mw + mt * 16 + g;
#pragma unroll
        for (int nt = 0; nt < 8; nt++) {
            const int n = n0 + nw + nt * 8 + 2 * tig;
            float2 v0, v1;
            v0.x = acc[mt][nt][0] * alpha;
            v0.y = acc[mt][nt][1] * alpha;
            v1.x = acc[mt][nt][2] * alpha;
            v1.y = acc[mt][nt][3] * alpha;
            if (bias) {
                float bx = bias[n], by = bias[n + 1];
                v0.x += bx; v0.y += by;
                v1.x += bx; v1.y += by;
            }
            if (round_out) {
                v0.x = tf32_rn(v0.x); v0.y = tf32_rn(v0.y);
                v1.x = tf32_rn(v1.x); v1.y = tf32_rn(v1.y);
            }
            *(float2*)(C + (long long)m * N + n)       = v0;
            *(float2*)(C + (long long)(m + 8) * N + n) = v1;
        }
    }
}

// ---------------------------------------------------------------------------
// tf32-round copy (for x)
// ---------------------------------------------------------------------------
__global__ void __launch_bounds__(256)
round_tf32_kernel(const float* __restrict__ in, float* __restrict__ out)
{
    size_t i = (size_t)blockIdx.x * blockDim.x + threadIdx.x;
    float4 v = ((const float4*)in)[i];
    v.x = tf32_rn(v.x); v.y = tf32_rn(v.y); v.z = tf32_rn(v.z); v.w = tf32_rn(v.w);
    ((float4*)out)[i] = v;
}

// ---------------------------------------------------------------------------
// Batched transpose: in [R,C] -> out [C,R], optional tf32 rounding
// ---------------------------------------------------------------------------
__global__ void __launch_bounds__(256)
transpose_kernel(const float* __restrict__ in, float* __restrict__ out,
                 int R, int C, long long sIn, long long sOut, int do_round)
{
    __shared__ float t[32][33];
    in  += (long long)blockIdx.z * sIn;
    out += (long long)blockIdx.z * sOut;
    const int c0 = blockIdx.x * 32, r0 = blockIdx.y * 32;
#pragma unroll
    for (int i = 0; i < 32; i += 8)
        t[threadIdx.y + i][threadIdx.x] =
            in[(long long)(r0 + threadIdx.y + i) * C + c0 + threadIdx.x];
    __syncthreads();
#pragma unroll
    for (int i = 0; i < 32; i += 8) {
        float v = t[threadIdx.x][threadIdx.y + i];
        if (do_round) v = tf32_rn(v);
        out[(long long)(c0 + threadIdx.y + i) * R + r0 + threadIdx.x] = v;
    }
}

// ---------------------------------------------------------------------------
// Softmax over the QUERY axis (axis=-2). Block = 32 k-columns x 8 q-segments
// (256 threads). grid = (SEQ/32, BATCH) = 256 blocks. Writes tf32-rounded.
// ---------------------------------------------------------------------------
__global__ void __launch_bounds__(256)
softmax_over_q_kernel(float* __restrict__ scores)
{
    __shared__ float red[8][32];
    const int b = blockIdx.y;
    const int lane = threadIdx.x & 31;
    const int seg  = threadIdx.x >> 5;          // 0..7
    const int k = blockIdx.x * 32 + lane;
    float* p = scores + (long long)b * SEQ * SEQ + k;
    const int q0 = seg * (SEQ / 8);
    const int q1 = q0 + (SEQ / 8);

    float m = -INFINITY;
    for (int q = q0; q < q1; q++) m = fmaxf(m, p[(long long)q * SEQ]);
    red[seg][lane] = m;
    __syncthreads();
    float mm = -INFINITY;
#pragma unroll
    for (int s = 0; s < 8; s++) mm = fmaxf(mm, red[s][lane]);
    __syncthreads();

    float sum = 0.0f;
    for (int q = q0; q < q1; q++) sum += expf(p[(long long)q * SEQ] - mm);
    red[seg][lane] = sum;
    __syncthreads();
    float tot = 0.0f;
#pragma unroll
    for (int s = 0; s < 8; s++) tot += red[s][lane];
    const float inv = 1.0f / tot;

    for (int q = q0; q < q1; q++) {
        float v = expf(p[(long long)q * SEQ] - mm) * inv;
        p[(long long)q * SEQ] = tf32_rn(v);
    }
}

// ---------------------------------------------------------------------------
// Launcher
// ---------------------------------------------------------------------------
extern "C" void kernel_launch(void* const* d_in, const int* in_sizes, int n_in,
                              void* d_out, int out_size)
{
    const float* x  = (const float*)d_in[0];
    const float* Wq = (const float*)d_in[1];
    const float* bq = (const float*)d_in[2];
    const float* Wk = (const float*)d_in[3];
    const float* bk = (const float*)d_in[4];
    const float* Wv = (const float*)d_in[5];
    const float* bv = (const float*)d_in[6];
    const float* Wo = (const float*)d_in[7];
    const float* bo = (const float*)d_in[8];
    float* out = (float*)d_out;

    float *xr, *q, *k, *v, *vt, *sc, *ctx, *wqt, *wkt, *wvt, *wot;
    cudaGetSymbolAddress((void**)&xr,  g_x);
    cudaGetSymbolAddress((void**)&q,   g_q);
    cudaGetSymbolAddress((void**)&k,   g_k);
    cudaGetSymbolAddress((void**)&v,   g_v);
    cudaGetSymbolAddress((void**)&vt,  g_vt);
    cudaGetSymbolAddress((void**)&sc,  g_sc);
    cudaGetSymbolAddress((void**)&ctx, g_ctx);
    cudaGetSymbolAddress((void**)&wqt, g_wqt);
    cudaGetSymbolAddress((void**)&wkt, g_wkt);
    cudaGetSymbolAddress((void**)&wvt, g_wvt);
    cudaGetSymbolAddress((void**)&wot, g_wot);

    cudaFuncSetAttribute(gemm_tf32_kernel,
                         cudaFuncAttributeMaxDynamicSharedMemorySize, GEMM_SMEM);

    const int MS = BATCH * SEQ;                        // 8192
    const long long sQK = (long long)SEQ * DKDIM;
    const long long sSS = (long long)SEQ * SEQ;
    const float inv_sqrt_dk = 1.0f / 32.0f;

    // 0) round x to tf32, transpose+round weights
    round_tf32_kernel<<<(BATCH * SEQ * FDIM / 4) / 256, 256>>>(x, xr);
    {
        dim3 blk(32, 8);
        dim3 g1(DKDIM / 32, FDIM / 32, 1);
        transpose_kernel<<<g1, blk>>>(Wq, wqt, FDIM, DKDIM, 0, 0, 1);
        transpose_kernel<<<g1, blk>>>(Wk, wkt, FDIM, DKDIM, 0, 0, 1);
        transpose_kernel<<<g1, blk>>>(Wv, wvt, FDIM, DKDIM, 0, 0, 1);
        dim3 g2(FDIM / 32, DKDIM / 32, 1);
        transpose_kernel<<<g2, blk>>>(Wo, wot, DKDIM, FDIM, 0, 0, 1);
    }

    // 1) projections: [8192,1024] = xr * W^T + b  (outputs tf32-rounded)
    {
        dim3 grd(DKDIM / BN, MS / BM, 1);
        gemm_tf32_kernel<<<grd, GEMM_THREADS, GEMM_SMEM>>>(xr, wqt, bq, q, MS, DKDIM, FDIM, 0, 0, 0, 1.0f, 1);
        gemm_tf32_kernel<<<grd, GEMM_THREADS, GEMM_SMEM>>>(xr, wkt, bk, k, MS, DKDIM, FDIM, 0, 0, 0, 1.0f, 1);
        gemm_tf32_kernel<<<grd, GEMM_THREADS, GEMM_SMEM>>>(xr, wvt, bv, v, MS, DKDIM, FDIM, 0, 0, 0, 1.0f, 1);
    }

    // 2) scores = Q K^T / sqrt(dk)   (batched)
    {
        dim3 grd(SEQ / BN, SEQ / BM, BATCH);
        gemm_tf32_kernel<<<grd, GEMM_THREADS, GEMM_SMEM>>>(q, k, nullptr, sc, SEQ, SEQ, DKDIM,
                                                           sQK, sQK, sSS, inv_sqrt_dk, 0);
    }

    // 3) softmax over query axis (writes tf32-rounded attn)
    softmax_over_q_kernel<<<dim3(SEQ / 32, BATCH), 256>>>(sc);

    // 3b) V^T (per batch) for the attn*V GEMM
    {
        dim3 blk(32, 8);
        dim3 g(DKDIM / 32, SEQ / 32, BATCH);
        transpose_kernel<<<g, blk>>>(v, vt, SEQ, DKDIM, sQK, sQK, 0);
    }

    // 4) ctx = attn * V   (batched; B = V^T [DK, S] K-major)
    {
        dim3 grd(DKDIM / BN, SEQ / BM, BATCH);
        gemm_tf32_kernel<<<grd, GEMM_THREADS, GEMM_SMEM>>>(sc, vt, nullptr, ctx, SEQ, DKDIM, SEQ,
                                                           sSS, sQK, sQK, 1.0f, 1);
    }

    // 5) out = ctx * Wo + bo
    {
        dim3 grd(FDIM / BN, MS / BM, 1);
        gemm_tf32_kernel<<<grd, GEMM_THREADS, GEMM_SMEM>>>(ctx, wot, bo, out, MS, FDIM, DKDIM,
                                                           0, 0, 0, 1.0f, 0);
    }
}

// round 6
// speedup vs baseline: 2.2067x; 1.8651x over previous
#include <cuda_runtime.h>
#include <cuda_fp16.h>
#include <cstdint>
#include <math.h>

// ---------------------------------------------------------------------------
// Problem constants
// ---------------------------------------------------------------------------
#define BATCH 4
#define SEQ   2048
#define FDIM  1024
#define DKDIM 1024

// ---------------------------------------------------------------------------
// fp16 mma.sync GEMM tiling: CTA 128x256, warp 64x64, BK=64, 3 stages
// ---------------------------------------------------------------------------
#define BM 128
#define BN 256
#define BK 64
#define STAGES 3
#define GEMM_THREADS 256

#define ROWH 72                                  // padded row length in halves (BK + 8)
#define A_STAGE_HALVES (BM * ROWH)               // 9216
#define B_STAGE_HALVES (BN * ROWH)               // 18432
#define STAGE_HALVES   (A_STAGE_HALVES + B_STAGE_HALVES)
#define GEMM_SMEM      (STAGES * STAGE_HALVES * 2)   // 165,888 B

// ---------------------------------------------------------------------------
// Scratch (device globals — no dynamic allocation allowed)
// ---------------------------------------------------------------------------
__device__ __half g_xh [(size_t)BATCH * SEQ * FDIM];
__device__ __half g_q  [(size_t)BATCH * SEQ * DKDIM];
__device__ __half g_k  [(size_t)BATCH * SEQ * DKDIM];
__device__ __half g_v  [(size_t)BATCH * SEQ * DKDIM];
__device__ __half g_vt [(size_t)BATCH * DKDIM * SEQ];
__device__ __half g_sc [(size_t)BATCH * SEQ * SEQ];
__device__ __half g_ctx[(size_t)BATCH * SEQ * DKDIM];
__device__ __half g_wqt[(size_t)DKDIM * FDIM];
__device__ __half g_wkt[(size_t)DKDIM * FDIM];
__device__ __half g_wvt[(size_t)DKDIM * FDIM];
__device__ __half g_wot[(size_t)FDIM * DKDIM];

// ---------------------------------------------------------------------------
// Helpers
// ---------------------------------------------------------------------------
__device__ __forceinline__ uint32_t smem_u32(const void* p) {
    uint32_t a;
    asm("{ .reg .u64 t; cvta.to.shared.u64 t, %1; cvt.u32.u64 %0, t; }" : "=r"(a) : "l"(p));
    return a;
}
__device__ __forceinline__ void cp_async16(uint32_t dst, const void* src) {
    asm volatile("cp.async.cg.shared.global [%0], [%1], 16;" :: "r"(dst), "l"(src) : "memory");
}
__device__ __forceinline__ void cp_commit() {
    asm volatile("cp.async.commit_group;" ::: "memory");
}
__device__ __forceinline__ void cp_wait_1() {
    asm volatile("cp.async.wait_group 1;" ::: "memory");
}
__device__ __forceinline__ void ldmatrix_x4(uint32_t* r, uint32_t addr) {
    asm volatile("ldmatrix.sync.aligned.m8n8.x4.shared.b16 {%0,%1,%2,%3}, [%4];"
                 : "=r"(r[0]), "=r"(r[1]), "=r"(r[2]), "=r"(r[3]) : "r"(addr));
}
__device__ __forceinline__ void mma_f16(float* d, const uint32_t* a,
                                        uint32_t b0, uint32_t b1) {
    asm volatile(
        "mma.sync.aligned.m16n8k16.row.col.f32.f16.f16.f32 "
        "{%0,%1,%2,%3}, {%4,%5,%6,%7}, {%8,%9}, {%0,%1,%2,%3};"
        : "+f"(d[0]), "+f"(d[1]), "+f"(d[2]), "+f"(d[3])
        : "r"(a[0]), "r"(a[1]), "r"(a[2]), "r"(a[3]), "r"(b0), "r"(b1));
}

// ---------------------------------------------------------------------------
// fp16 tensor-core GEMM:  C = alpha * A * B^T + bias
//   A: [M,K] half row-major (batched by sA)
//   B: [N,K] half row-major (batched by sB)
//   C: [M,N] row-major: half if c_half else float (batched by sC)
// M % 128 == 0, N % 256 == 0, K % 64 == 0 (holds for every shape here).
// ---------------------------------------------------------------------------
__global__ void __launch_bounds__(GEMM_THREADS, 1)
gemm_f16_kernel(const __half* __restrict__ A, const __half* __restrict__ B,
                const float* __restrict__ bias, void* __restrict__ Cv,
                int M, int N, int K,
                long long sA, long long sB, long long sC,
                float alpha, int c_half)
{
    extern __shared__ __half sm[];
    const int tid = threadIdx.x;
    const int wid = tid >> 5;
    const int lane = tid & 31;
    const int g   = lane >> 2;         // 0..7
    const int tig = lane & 3;          // 0..3
    const int mw = (wid & 1) * 64;     // warp m offset (2 rows of warps)
    const int nw = (wid >> 1) * 64;    // warp n offset (4 cols of warps)

    A += (long long)blockIdx.z * sA;
    B += (long long)blockIdx.z * sB;
    const int m0 = blockIdx.y * BM;
    const int n0 = blockIdx.x * BN;

    float acc[4][8][4];
#pragma unroll
    for (int mt = 0; mt < 4; mt++)
#pragma unroll
        for (int nt = 0; nt < 8; nt++)
#pragma unroll
            for (int r = 0; r < 4; r++) acc[mt][nt][r] = 0.0f;

    const uint32_t sm_base = smem_u32(sm);
    const int KT = K / BK;

    auto load_stage = [&](int p) {
        const uint32_t base = sm_base + (uint32_t)((p % STAGES) * STAGE_HALVES) * 2u;
        const uint32_t bbase = base + A_STAGE_HALVES * 2u;
        const int k0 = p * BK;
#pragma unroll
        for (int t = 0; t < 4; t++) {                // A: 1024 chunks of 16B
            int c = tid + t * GEMM_THREADS;
            int r = c >> 3, kc = c & 7;
            cp_async16(base + (uint32_t)(r * ROWH + kc * 8) * 2u,
                       A + (long long)(m0 + r) * K + k0 + kc * 8);
        }
#pragma unroll
        for (int t = 0; t < 8; t++) {                // B: 2048 chunks of 16B
            int c = tid + t * GEMM_THREADS;
            int r = c >> 3, kc = c & 7;
            cp_async16(bbase + (uint32_t)(r * ROWH + kc * 8) * 2u,
                       B + (long long)(n0 + r) * K + k0 + kc * 8);
        }
    };

    load_stage(0); cp_commit();
    load_stage(1); cp_commit();

    // ldmatrix per-lane row/k selects
    const int row_a  = ((lane >> 3) & 1) * 8 + (lane & 7);   // matrices 0/1: m, m+8
    const int kadd_a = ((lane >> 4) & 1) * 8;                //   2/3: +8 k
    const int row_b  = ((lane >> 4) & 1) * 8 + (lane & 7);   // matrices 0/1: n; 2/3: n+8
    const int kadd_b = ((lane >> 3) & 1) * 8;                //   1/3: +8 k

    for (int kt = 0; kt < KT; kt++) {
        cp_wait_1();                     // stage kt resident
        __syncthreads();                 // all warps done with stage kt-1

        if (kt + 2 < KT) load_stage(kt + 2);
        cp_commit();

        const uint32_t sa  = sm_base + (uint32_t)((kt % STAGES) * STAGE_HALVES) * 2u;
        const uint32_t sbp = sa + A_STAGE_HALVES * 2u;
#pragma unroll
        for (int kk = 0; kk < 4; kk++) {
            const int k16 = kk * 16;
            uint32_t a[4][4], b[4][4];
#pragma unroll
            for (int mt = 0; mt < 4; mt++)
                ldmatrix_x4(a[mt],
                    sa + (uint32_t)((mw + mt * 16 + row_a) * ROWH + k16 + kadd_a) * 2u);
#pragma unroll
            for (int i = 0; i < 4; i++)
                ldmatrix_x4(b[i],
                    sbp + (uint32_t)((nw + i * 16 + row_b) * ROWH + k16 + kadd_b) * 2u);
#pragma unroll
            for (int mt = 0; mt < 4; mt++)
#pragma unroll
                for (int nt = 0; nt < 8; nt++)
                    mma_f16(acc[mt][nt], a[mt],
                            b[nt >> 1][(nt & 1) * 2], b[nt >> 1][(nt & 1) * 2 + 1]);
        }
    }

    // ---- epilogue ----
#pragma unroll
    for (int mt = 0; mt < 4; mt++) {
        const int m = m0 + mw + mt * 16 + g;
#pragma unroll
        for (int nt = 0; nt < 8; nt++) {
            const int n = n0 + nw + nt * 8 + 2 * tig;
            float2 v0, v1;
            v0.x = acc[mt][nt][0] * alpha;
            v0.y = acc[mt][nt][1] * alpha;
            v1.x = acc[mt][nt][2] * alpha;
            v1.y = acc[mt][nt][3] * alpha;
            if (bias) {
                float bx = bias[n], by = bias[n + 1];
                v0.x += bx; v0.y += by;
                v1.x += bx; v1.y += by;
            }
            if (c_half) {
                __half* C = (__half*)Cv + (long long)blockIdx.z * sC;
                *(__half2*)(C + (long long)m * N + n)       = __floats2half2_rn(v0.x, v0.y);
                *(__half2*)(C + (long long)(m + 8) * N + n) = __floats2half2_rn(v1.x, v1.y);
            } else {
                float* C = (float*)Cv + (long long)blockIdx.z * sC;
                *(float2*)(C + (long long)m * N + n)       = v0;
                *(float2*)(C + (long long)(m + 8) * N + n) = v1;
            }
        }
    }
}

// ---------------------------------------------------------------------------
// fp32 -> fp16 copy (for x)
// ---------------------------------------------------------------------------
__global__ void __launch_bounds__(256)
f2h_kernel(const float* __restrict__ in, __half* __restrict__ out)
{
    size_t i = (size_t)blockIdx.x * blockDim.x + threadIdx.x;
    float4 v = ((const float4*)in)[i];
    ((__half2*)out)[2 * i]     = __floats2half2_rn(v.x, v.y);
    ((__half2*)out)[2 * i + 1] = __floats2half2_rn(v.z, v.w);
}

// ---------------------------------------------------------------------------
// Transpose fp32 [R,C] -> half [C,R]  (weights)
// ---------------------------------------------------------------------------
__global__ void __launch_bounds__(256)
transpose_f2h_kernel(const float* __restrict__ in, __half* __restrict__ out,
                     int R, int C)
{
    __shared__ float t[32][33];
    const int c0 = blockIdx.x * 32, r0 = blockIdx.y * 32;
#pragma unroll
    for (int i = 0; i < 32; i += 8)
        t[threadIdx.y + i][threadIdx.x] =
            in[(long long)(r0 + threadIdx.y + i) * C + c0 + threadIdx.x];
    __syncthreads();
#pragma unroll
    for (int i = 0; i < 32; i += 8)
        out[(long long)(c0 + threadIdx.y + i) * R + r0 + threadIdx.x] =
            __float2half_rn(t[threadIdx.x][threadIdx.y + i]);
}

// ---------------------------------------------------------------------------
// Batched transpose half [R,C] -> half [C,R]  (V^T)
// ---------------------------------------------------------------------------
__global__ void __launch_bounds__(256)
transpose_h_kernel(const __half* __restrict__ in, __half* __restrict__ out,
                   int R, int C, long long sIn, long long sOut)
{
    __shared__ __half t[32][34];
    in  += (long long)blockIdx.z * sIn;
    out += (long long)blockIdx.z * sOut;
    const int c0 = blockIdx.x * 32, r0 = blockIdx.y * 32;
#pragma unroll
    for (int i = 0; i < 32; i += 8)
        t[threadIdx.y + i][threadIdx.x] =
            in[(long long)(r0 + threadIdx.y + i) * C + c0 + threadIdx.x];
    __syncthreads();
#pragma unroll
    for (int i = 0; i < 32; i += 8)
        out[(long long)(c0 + threadIdx.y + i) * R + r0 + threadIdx.x] =
            t[threadIdx.x][threadIdx.y + i];
}

// ---------------------------------------------------------------------------
// Softmax over the QUERY axis (axis=-2), half in/out, fp32 math.
// Block = 32 k-columns x 8 q-segments. grid = (SEQ/32, BATCH).
// ---------------------------------------------------------------------------
__global__ void __launch_bounds__(256)
softmax_over_q_kernel(__half* __restrict__ scores)
{
    __shared__ float red[8][32];
    const int b = blockIdx.y;
    const int lane = threadIdx.x & 31;
    const int seg  = threadIdx.x >> 5;          // 0..7
    const int k = blockIdx.x * 32 + lane;
    __half* p = scores + (long long)b * SEQ * SEQ + k;
    const int q0 = seg * (SEQ / 8);
    const int q1 = q0 + (SEQ / 8);

    float m = -INFINITY;
    for (int q = q0; q < q1; q++) m = fmaxf(m, __half2float(p[(long long)q * SEQ]));
    red[seg][lane] = m;
    __syncthreads();
    float mm = -INFINITY;
#pragma unroll
    for (int s = 0; s < 8; s++) mm = fmaxf(mm, red[s][lane]);
    __syncthreads();

    float sum = 0.0f;
    for (int q = q0; q < q1; q++) sum += expf(__half2float(p[(long long)q * SEQ]) - mm);
    red[seg][lane] = sum;
    __syncthreads();
    float tot = 0.0f;
#pragma unroll
    for (int s = 0; s < 8; s++) tot += red[s][lane];
    const float inv = 1.0f / tot;

    for (int q = q0; q < q1; q++) {
        float v = expf(__half2float(p[(long long)q * SEQ]) - mm) * inv;
        p[(long long)q * SEQ] = __float2half_rn(v);
    }
}

// ---------------------------------------------------------------------------
// Launcher
// ---------------------------------------------------------------------------
extern "C" void kernel_launch(void* const* d_in, const int* in_sizes, int n_in,
                              void* d_out, int out_size)
{
    const float* x  = (const float*)d_in[0];
    const float* Wq = (const float*)d_in[1];
    const float* bq = (const float*)d_in[2];
    const float* Wk = (const float*)d_in[3];
    const float* bk = (const float*)d_in[4];
    const float* Wv = (const float*)d_in[5];
    const float* bv = (const float*)d_in[6];
    const float* Wo = (const float*)d_in[7];
    const float* bo = (const float*)d_in[8];
    float* out = (float*)d_out;

    __half *xh, *q, *k, *v, *vt, *sc, *ctx, *wqt, *wkt, *wvt, *wot;
    cudaGetSymbolAddress((void**)&xh,  g_xh);
    cudaGetSymbolAddress((void**)&q,   g_q);
    cudaGetSymbolAddress((void**)&k,   g_k);
    cudaGetSymbolAddress((void**)&v,   g_v);
    cudaGetSymbolAddress((void**)&vt,  g_vt);
    cudaGetSymbolAddress((void**)&sc,  g_sc);
    cudaGetSymbolAddress((void**)&ctx, g_ctx);
    cudaGetSymbolAddress((void**)&wqt, g_wqt);
    cudaGetSymbolAddress((void**)&wkt, g_wkt);
    cudaGetSymbolAddress((void**)&wvt, g_wvt);
    cudaGetSymbolAddress((void**)&wot, g_wot);

    cudaFuncSetAttribute(gemm_f16_kernel,
                         cudaFuncAttributeMaxDynamicSharedMemorySize, GEMM_SMEM);

    const int MS = BATCH * SEQ;                        // 8192
    const long long sQK = (long long)SEQ * DKDIM;
    const long long sSS = (long long)SEQ * SEQ;
    const float inv_sqrt_dk = 1.0f / 32.0f;

    // 0) x -> half; weights transpose -> half
    f2h_kernel<<<(BATCH * SEQ * FDIM / 4) / 256, 256>>>(x, xh);
    {
        dim3 blk(32, 8);
        dim3 g1(DKDIM / 32, FDIM / 32, 1);
        transpose_f2h_kernel<<<g1, blk>>>(Wq, wqt, FDIM, DKDIM);
        transpose_f2h_kernel<<<g1, blk>>>(Wk, wkt, FDIM, DKDIM);
        transpose_f2h_kernel<<<g1, blk>>>(Wv, wvt, FDIM, DKDIM);
        dim3 g2(FDIM / 32, DKDIM / 32, 1);
        transpose_f2h_kernel<<<g2, blk>>>(Wo, wot, DKDIM, FDIM);
    }

    // 1) projections: [8192,1024] = xh * W^T + b  (half outputs)
    {
        dim3 grd(DKDIM / BN, MS / BM, 1);
        gemm_f16_kernel<<<grd, GEMM_THREADS, GEMM_SMEM>>>(xh, wqt, bq, q, MS, DKDIM, FDIM, 0, 0, 0, 1.0f, 1);
        gemm_f16_kernel<<<grd, GEMM_THREADS, GEMM_SMEM>>>(xh, wkt, bk, k, MS, DKDIM, FDIM, 0, 0, 0, 1.0f, 1);
        gemm_f16_kernel<<<grd, GEMM_THREADS, GEMM_SMEM>>>(xh, wvt, bv, v, MS, DKDIM, FDIM, 0, 0, 0, 1.0f, 1);
    }

    // 2) scores = Q K^T / sqrt(dk)   (batched, half output)
    {
        dim3 grd(SEQ / BN, SEQ / BM, BATCH);
        gemm_f16_kernel<<<grd, GEMM_THREADS, GEMM_SMEM>>>(q, k, nullptr, sc, SEQ, SEQ, DKDIM,
                                                          sQK, sQK, sSS, inv_sqrt_dk, 1);
    }

    // 3) softmax over query axis (half in/out)
    softmax_over_q_kernel<<<dim3(SEQ / 32, BATCH), 256>>>(sc);

    // 3b) V^T per batch
    {
        dim3 blk(32, 8);
        dim3 g(DKDIM / 32, SEQ / 32, BATCH);
        transpose_h_kernel<<<g, blk>>>(v, vt, SEQ, DKDIM, sQK, sQK);
    }

    // 4) ctx = attn * V   (batched; B = V^T [DK,S] K-major; half output)
    {
        dim3 grd(DKDIM / BN, SEQ / BM, BATCH);
        gemm_f16_kernel<<<grd, GEMM_THREADS, GEMM_SMEM>>>(sc, vt, nullptr, ctx, SEQ, DKDIM, SEQ,
                                                          sSS, sQK, sQK, 1.0f, 1);
    }

    // 5) out = ctx * Wo + bo   (fp32 output)
    {
        dim3 grd(FDIM / BN, MS / BM, 1);
        gemm_f16_kernel<<<grd, GEMM_THREADS, GEMM_SMEM>>>(ctx, wot, bo, out, MS, FDIM, DKDIM,
                                                          0, 0, 0, 1.0f, 0);
    }
}